// round 17
// baseline (speedup 1.0000x reference)
#include <cuda_runtime.h>
#include <cuda_fp16.h>
#include <cuda_bf16.h>
#include <cstdint>

// Problem constants
#define Bb 4
#define Cc 256
#define C2v 128
#define Nn 4096

// ---------------------------------------------------------------------------
// Scratch (__device__ globals; allocation-free rule)
// ---------------------------------------------------------------------------
__device__ __half         g_xh[(size_t)Bb * Nn * 256];   // [B][n][c] fp16 x (transposed)
__device__ __half         g_wh[(size_t)512 * 256];       // [o][c]: q 0-127, k 128-255, v 256-511
__device__ __half         g_qc[(size_t)Bb * Nn * 128];   // [B][n][128] fp16 q
__device__ __half         g_kc[(size_t)Bb * Nn * 128];   // [B][n][128] fp16 masked k
__device__ __nv_bfloat16  g_vb[(size_t)Bb * Cc * Nn];    // [B][c][n]  (K-major for AV)
__device__ __nv_bfloat16  g_attb[(size_t)Bb * Nn * Nn];  // P = exp(S), bf16
__device__ float          g_sumexp[(size_t)Bb * Nn * 32];// per-row per-chunk sum of exp

// ---------------------------------------------------------------------------
// Helpers
// ---------------------------------------------------------------------------
__device__ __forceinline__ uint32_t smem_u32(const void* p) {
    uint32_t a;
    asm("{ .reg .u64 t; cvta.to.shared.u64 t, %1; cvt.u32.u64 %0, t; }" : "=r"(a) : "l"(p));
    return a;
}
__device__ __forceinline__ void cp_async16(uint32_t dst, const void* src) {
    asm volatile("cp.async.cg.shared.global [%0], [%1], 16;" :: "r"(dst), "l"(src));
}
#define CP_COMMIT() asm volatile("cp.async.commit_group;" ::: "memory")
template <int N>
__device__ __forceinline__ void cp_wait() {
    asm volatile("cp.async.wait_group %0;" :: "n"(N) : "memory");
}
__device__ __forceinline__ void ldmx4(uint32_t* r, uint32_t addr) {
    asm volatile("ldmatrix.sync.aligned.m8n8.x4.shared.b16 {%0,%1,%2,%3}, [%4];"
        : "=r"(r[0]), "=r"(r[1]), "=r"(r[2]), "=r"(r[3]) : "r"(addr));
}
__device__ __forceinline__ void mma16816(float* d, const uint32_t* a, uint32_t b0, uint32_t b1) {
    asm volatile(
        "mma.sync.aligned.m16n8k16.row.col.f32.f16.f16.f32 "
        "{%0,%1,%2,%3},{%4,%5,%6,%7},{%8,%9},{%0,%1,%2,%3};"
        : "+f"(d[0]), "+f"(d[1]), "+f"(d[2]), "+f"(d[3])
        : "r"(a[0]), "r"(a[1]), "r"(a[2]), "r"(a[3]), "r"(b0), "r"(b1));
}
__device__ __forceinline__ void mma16816bf(float* d, const uint32_t* a, uint32_t b0, uint32_t b1) {
    asm volatile(
        "mma.sync.aligned.m16n8k16.row.col.f32.bf16.bf16.f32 "
        "{%0,%1,%2,%3},{%4,%5,%6,%7},{%8,%9},{%0,%1,%2,%3};"
        : "+f"(d[0]), "+f"(d[1]), "+f"(d[2]), "+f"(d[3])
        : "r"(a[0]), "r"(a[1]), "r"(a[2]), "r"(a[3]), "r"(b0), "r"(b1));
}

// Fast exp: 1 FFMA + 1 MUFU (ex2.approx).
__device__ __forceinline__ float fexp(float x) {
    return __expf(x);
}

// ---------------------------------------------------------------------------
// GEMM tile geometry: BK=32, smem rows stride 80B.
// ---------------------------------------------------------------------------
#define ROWB 80                 // bytes per smem tile row
#define TILE_B (128 * ROWB)     // 10240 per 128-row tile
#define STAGE_PAIR (2 * TILE_B) // 20480 per stage (A+B), 128-row kernels
#define NSTAGE 3
#define DYN_SMEM (NSTAGE * STAGE_PAIR)        // 61440 (projmma)

// qk smem layout: resident A (4 k-tiles) + 3-stage B ring + sred + pst
#define QK_BOFF 40960u          // B ring base (after 4 A k-tiles)
#define QK_SRED 71680u          // 4*128 floats
#define QK_PST  73728u          // 128 x PSTR bf16
#define PSTR 136                // P staging row stride (halves), conflict-free
#define DYN_QK  108544

// av (512-thread) smem: stage = A(128 rows,10240) + B(256 rows,20480)
#define AV_ATILE 10240
#define AV_BTILE (256 * ROWB)   // 20480
#define AV_STAGE (AV_ATILE + AV_BTILE)  // 30720
#define DYN_AV (NSTAGE * AV_STAGE)      // 92160

// Load one 128x32 16-bit tile (256 threads, 2 passes).
__device__ __forceinline__ void load_tile(uint32_t dst, const __half* src,
                                          size_t stride, int tid)
{
    #pragma unroll
    for (int i = 0; i < 2; i++) {
        int idx = tid + i * 256;          // 0..511
        int row = idx >> 2, c16 = idx & 3;
        cp_async16(dst + row * ROWB + c16 * 16, src + (size_t)row * stride + c16 * 8);
    }
}

// 512-thread loaders: 128-row tile (1 pass), 256-row tile (2 passes).
__device__ __forceinline__ void load_a512(uint32_t dst, const __half* src,
                                          size_t stride, int tid)
{
    int row = tid >> 2, c16 = tid & 3;
    cp_async16(dst + row * ROWB + c16 * 16, src + (size_t)row * stride + c16 * 8);
}
__device__ __forceinline__ void load_b512(uint32_t dst, const __half* src,
                                          size_t stride, int tid)
{
    #pragma unroll
    for (int i = 0; i < 2; i++) {
        int idx = tid + i * 512;          // 0..1023
        int row = idx >> 2, c16 = idx & 3;
        cp_async16(dst + row * ROWB + c16 * 16, src + (size_t)row * stride + c16 * 8);
    }
}

// One BK=32 compute step (fp16 operands). wx may range 0..7 (B tile 256 rows).
__device__ __forceinline__ void warp_mma_step(float acc[4][4][4], uint32_t abase,
                                              uint32_t bbase, int wy, int wx, int lane)
{
    #pragma unroll
    for (int ks = 0; ks < 2; ks++) {
        uint32_t a[4][4];
        #pragma unroll
        for (int mf = 0; mf < 4; mf++) {
            int row = wy * 64 + mf * 16 + (lane & 15);
            ldmx4(a[mf], abase + row * ROWB + ks * 32 + ((lane >> 4) << 4));
        }
        uint32_t bf[2][4];
        #pragma unroll
        for (int np = 0; np < 2; np++) {
            int row = wx * 32 + np * 16 + (lane & 7) + ((lane >> 4) << 3);
            ldmx4(bf[np], bbase + row * ROWB + ks * 32 + (((lane >> 3) & 1) << 4));
        }
        #pragma unroll
        for (int mf = 0; mf < 4; mf++)
            #pragma unroll
            for (int nf = 0; nf < 4; nf++)
                mma16816(acc[mf][nf], a[mf],
                         bf[nf >> 1][(nf & 1) * 2], bf[nf >> 1][(nf & 1) * 2 + 1]);
    }
}

// Same, bf16 operands
__device__ __forceinline__ void warp_mma_step_bf(float acc[4][4][4], uint32_t abase,
                                                 uint32_t bbase, int wy, int wx, int lane)
{
    #pragma unroll
    for (int ks = 0; ks < 2; ks++) {
        uint32_t a[4][4];
        #pragma unroll
        for (int mf = 0; mf < 4; mf++) {
            int row = wy * 64 + mf * 16 + (lane & 15);
            ldmx4(a[mf], abase + row * ROWB + ks * 32 + ((lane >> 4) << 4));
        }
        uint32_t bf[2][4];
        #pragma unroll
        for (int np = 0; np < 2; np++) {
            int row = wx * 32 + np * 16 + (lane & 7) + ((lane >> 4) << 3);
            ldmx4(bf[np], bbase + row * ROWB + ks * 32 + (((lane >> 3) & 1) << 4));
        }
        #pragma unroll
        for (int mf = 0; mf < 4; mf++)
            #pragma unroll
            for (int nf = 0; nf < 4; nf++)
                mma16816bf(acc[mf][nf], a[mf],
                           bf[nf >> 1][(nf & 1) * 2], bf[nf >> 1][(nf & 1) * 2 + 1]);
    }
}

// ---------------------------------------------------------------------------
// Kernel 0a: xcvt — transpose-convert x [B][c][n] fp32 -> g_xh [B][n][c] fp16
// ---------------------------------------------------------------------------
__global__ __launch_bounds__(256) void xcvt_kernel(const float* __restrict__ x)
{
    __shared__ float ts[64][65];
    const int b = blockIdx.z, n0 = blockIdx.x * 64, c0 = blockIdx.y * 64;
    const int tid = threadIdx.x;

    #pragma unroll
    for (int i = 0; i < 4; i++) {
        int idx = tid + i * 256;          // 0..1023
        int r = idx >> 4, f4 = idx & 15;  // row c-local, 16B col group
        float4 v = *reinterpret_cast<const float4*>(
            x + ((size_t)b * Cc + c0 + r) * Nn + n0 + f4 * 4);
        ts[r][f4 * 4 + 0] = v.x;
        ts[r][f4 * 4 + 1] = v.y;
        ts[r][f4 * 4 + 2] = v.z;
        ts[r][f4 * 4 + 3] = v.w;
    }
    __syncthreads();

    const int nr = tid >> 2;
    #pragma unroll
    for (int i = 0; i < 2; i++) {
        int c8 = ((tid & 3) * 2 + i) * 8;
        __half h8[8];
        #pragma unroll
        for (int j = 0; j < 8; j++) h8[j] = __float2half(ts[c8 + j][nr]);
        size_t off = ((size_t)b * Nn + n0 + nr) * 256 + c0 + c8;
        *reinterpret_cast<float4*>(g_xh + off) = *reinterpret_cast<float4*>(h8);
    }
}

// ---------------------------------------------------------------------------
// Kernel 0b: wcvt — Wq|Wk|Wv fp32 -> g_wh fp16 [512][256]
// ---------------------------------------------------------------------------
__global__ __launch_bounds__(256) void wcvt_kernel(
    const float* __restrict__ Wq, const float* __restrict__ Wk,
    const float* __restrict__ Wv)
{
    int e4 = blockIdx.x * 256 + threadIdx.x;   // 0..32767
    int row = e4 >> 6, col4 = (e4 & 63) * 4;
    const float* src = (row < 128) ? (Wq + (size_t)row * 256)
                     : (row < 256) ? (Wk + (size_t)(row - 128) * 256)
                                   : (Wv + (size_t)(row - 256) * 256);
    float4 v = *reinterpret_cast<const float4*>(src + col4);
    __half h4[4];
    h4[0] = __float2half(v.x); h4[1] = __float2half(v.y);
    h4[2] = __float2half(v.z); h4[3] = __float2half(v.w);
    *reinterpret_cast<float2*>(g_wh + (size_t)row * 256 + col4) =
        *reinterpret_cast<float2*>(h4);
}

// ---------------------------------------------------------------------------
// Kernel 1: projections via mma.sync fp16, single-term K=256 (NK=8).
// ---------------------------------------------------------------------------
#define VPAD 136   // smem v-transpose row stride (halves)

__global__ __launch_bounds__(256, 2) void projmma_kernel(
    const float* __restrict__ mask, const float* __restrict__ skin,
    const float* __restrict__ bq, const float* __restrict__ bk,
    const float* __restrict__ bv)
{
    extern __shared__ __align__(128) char dynsm[];
    __shared__ float fm[128];
    const int b = blockIdx.z, m0 = blockIdx.y * 128, oblk = blockIdx.x;
    const int tid = threadIdx.x, wid = tid >> 5, lane = tid & 31;
    const int wy = wid >> 2, wx = wid & 3;
    const uint32_t sb = smem_u32(dynsm);

    const int NK = 8;
    const __half* Asrc = g_xh + ((size_t)b * Nn + m0) * 256;
    const __half* Bsrc = g_wh + (size_t)oblk * 128 * 256;

    if (oblk == 1 && tid < 128)
        fm[tid] = (1.0f - mask[b * Nn + m0 + tid]) * skin[b * Nn + m0 + tid];

    #pragma unroll
    for (int s = 0; s < 2; s++) {
        uint32_t st = sb + s * STAGE_PAIR;
        load_tile(st, Asrc + s * 32, 256, tid);
        load_tile(st + TILE_B, Bsrc + s * 32, 256, tid);
        CP_COMMIT();
    }

    float acc[4][4][4] = {};
    #pragma unroll 1
    for (int s = 0; s < NK; s++) {
        if (s < NK - 1) cp_wait<1>(); else cp_wait<0>();
        __syncthreads();
        if (s + 2 < NK) {
            uint32_t ld = sb + (uint32_t)((s + 2) % NSTAGE) * STAGE_PAIR;
            load_tile(ld, Asrc + (s + 2) * 32, 256, tid);
            load_tile(ld + TILE_B, Bsrc + (s + 2) * 32, 256, tid);
            CP_COMMIT();
        }
        const uint32_t st = sb + (uint32_t)(s % NSTAGE) * STAGE_PAIR;
        warp_mma_step(acc, st, st + TILE_B, wy, wx, lane);
    }

    // Epilogue
    const float* biasp = (oblk == 0) ? bq : (oblk == 1) ? bk
                       : (oblk == 2) ? bv : (bv + 128);
    float bias0[4], bias1[4];
    #pragma unroll
    for (int nf = 0; nf < 4; nf++) {
        int o = wx * 32 + nf * 8 + (lane & 3) * 2;
        bias0[nf] = biasp[o];
        bias1[nf] = biasp[o + 1];
    }

    if (oblk <= 1) {
        #pragma unroll
        for (int mf = 0; mf < 4; mf++) {
            const int rA = wy * 64 + mf * 16 + (lane >> 2);
            const int rB = rA + 8;
            float fA = 1.0f, fB = 1.0f;
            if (oblk == 1) { fA = fm[rA]; fB = fm[rB]; }
            #pragma unroll
            for (int nf = 0; nf < 4; nf++) {
                const int o = wx * 32 + nf * 8 + (lane & 3) * 2;
                float r0 = (acc[mf][nf][0] + bias0[nf]) * fA;
                float r1 = (acc[mf][nf][1] + bias1[nf]) * fA;
                float r2 = (acc[mf][nf][2] + bias0[nf]) * fB;
                float r3 = (acc[mf][nf][3] + bias1[nf]) * fB;
                __half* dst = (oblk == 0) ? g_qc : g_kc;
                size_t oa = ((size_t)b * Nn + m0 + rA) * 128 + o;
                size_t ob = ((size_t)b * Nn + m0 + rB) * 128 + o;
                *reinterpret_cast<__half2*>(dst + oa) = __floats2half2_rn(r0, r1);
                *reinterpret_cast<__half2*>(dst + ob) = __floats2half2_rn(r2, r3);
            }
        }
    } else {
        // v: bounce through smem [c][n] tile, then coalesced g_vb writes.
        __syncthreads();   // mainloop tiles dead; reuse dynsm
        __nv_bfloat16* vsm = reinterpret_cast<__nv_bfloat16*>(dynsm);
        #pragma unroll
        for (int mf = 0; mf < 4; mf++) {
            const int rA = wy * 64 + mf * 16 + (lane >> 2);   // n-local
            const int rB = rA + 8;
            #pragma unroll
            for (int nf = 0; nf < 4; nf++) {
                const int o = wx * 32 + nf * 8 + (lane & 3) * 2;   // c-local
                vsm[o * VPAD + rA]       = __float2bfloat16(acc[mf][nf][0] + bias0[nf]);
                vsm[(o + 1) * VPAD + rA] = __float2bfloat16(acc[mf][nf][1] + bias1[nf]);
                vsm[o * VPAD + rB]       = __float2bfloat16(acc[mf][nf][2] + bias0[nf]);
                vsm[(o + 1) * VPAD + rB] = __float2bfloat16(acc[mf][nf][3] + bias1[nf]);
            }
        }
        __syncthreads();
        const int c0r = (oblk - 2) * 128;
        #pragma unroll
        for (int i = 0; i < 8; i++) {
            int f4 = tid + i * 256;           // 0..2047
            int row = f4 >> 4, c8 = (f4 & 15) * 8;
            float4 v = *reinterpret_cast<float4*>(vsm + row * VPAD + c8);
            *reinterpret_cast<float4*>(
                g_vb + ((size_t)b * Cc + c0r + row) * Nn + m0 + c8) = v;
        }
    }
}

// ---------------------------------------------------------------------------
// Kernel 2: QK^T -> P = exp(S). Multi-chunk (4 n-chunks/block), resident A,
// 3-stage B ring at prefetch distance 2. grid (8, 32, B).
// ---------------------------------------------------------------------------
__global__ __launch_bounds__(256, 2) void qk_kernel()
{
    extern __shared__ __align__(128) char dynsm[];
    const int b = blockIdx.z, m0 = blockIdx.y * 128;
    const int nq = blockIdx.x;                       // 0..7 (quad of chunks)
    const int tid = threadIdx.x, wid = tid >> 5, lane = tid & 31;
    const int wy = wid >> 2, wx = wid & 3;
    const uint32_t sb = smem_u32(dynsm);

    const __half* Asrc = g_qc + ((size_t)b * Nn + m0) * 128;
    const __half* Bbase = g_kc + ((size_t)b * Nn + nq * 512) * 128;

    float* sred = reinterpret_cast<float*>(dynsm + QK_SRED);
    __nv_bfloat16* pst = reinterpret_cast<__nv_bfloat16*>(dynsm + QK_PST);

    // Prologue: resident A (4 k-tiles, one group), then B for t = 0,1.
    #pragma unroll
    for (int kt = 0; kt < 4; kt++)
        load_tile(sb + (uint32_t)kt * TILE_B, Asrc + kt * 32, 128, tid);
    CP_COMMIT();
    #pragma unroll
    for (int t = 0; t < 2; t++) {
        load_tile(sb + QK_BOFF + (uint32_t)t * TILE_B,
                  Bbase + (size_t)((t >> 2) * 128) * 128 + (t & 3) * 32, 128, tid);
        CP_COMMIT();
    }

    float acc[4][4][4] = {};
    #pragma unroll 1
    for (int t = 0; t < 16; t++) {
        if (t < 15) cp_wait<1>(); else cp_wait<0>();
        __syncthreads();
        if (t + 2 < 16) {
            int tp = t + 2;
            load_tile(sb + QK_BOFF + (uint32_t)(tp % 3) * TILE_B,
                      Bbase + (size_t)((tp >> 2) * 128) * 128 + (tp & 3) * 32, 128, tid);
            CP_COMMIT();
        }
        warp_mma_step(acc, sb + (uint32_t)(t & 3) * TILE_B,
                      sb + QK_BOFF + (uint32_t)(t % 3) * TILE_B, wy, wx, lane);

        if ((t & 3) == 3) {
            // ---- epilogue for chunk (t>>2): exp, stage P, row sums, writeout ----
            const int gch = nq * 4 + (t >> 2);       // global chunk 0..31
            const int n0 = gch * 128;

            float rsum[4][2];
            #pragma unroll
            for (int mf = 0; mf < 4; mf++) {
                int rA = wy * 64 + mf * 16 + (lane >> 2);
                int rB = rA + 8;
                float sA = 0.0f, sB = 0.0f;
                #pragma unroll
                for (int nf = 0; nf < 4; nf++) {
                    float p0 = fexp(acc[mf][nf][0]);
                    float p1 = fexp(acc[mf][nf][1]);
                    float p2 = fexp(acc[mf][nf][2]);
                    float p3 = fexp(acc[mf][nf][3]);
                    sA += p0 + p1; sB += p2 + p3;
                    int cl = wx * 32 + nf * 8 + (lane & 3) * 2;
                    *reinterpret_cast<__nv_bfloat162*>(pst + rA * PSTR + cl) = __floats2bfloat162_rn(p0, p1);
                    *reinterpret_cast<__nv_bfloat162*>(pst + rB * PSTR + cl) = __floats2bfloat162_rn(p2, p3);
                }
                rsum[mf][0] = sA; rsum[mf][1] = sB;
            }
            #pragma unroll
            for (int o = 1; o <= 2; o <<= 1)
                #pragma unroll
                for (int mf = 0; mf < 4; mf++) {
                    rsum[mf][0] += __shfl_xor_sync(0xffffffffu, rsum[mf][0], o);
                    rsum[mf][1] += __shfl_xor_sync(0xffffffffu, rsum[mf][1], o);
                }
            if ((lane & 3) == 0) {
                #pragma unroll
                for (int mf = 0; mf < 4; mf++) {
                    int rA = wy * 64 + mf * 16 + (lane >> 2);
                    sred[wx * 128 + rA]     = rsum[mf][0];
                    sred[wx * 128 + rA + 8] = rsum[mf][1];
                }
            }
            __syncthreads();
            if (tid < 128) {
                float se = sred[tid] + sred[128 + tid] + sred[256 + tid] + sred[384 + tid];
                g_sumexp[((size_t)b * Nn + m0 + tid) * 32 + gch] = se;
            }
            #pragma unroll
            for (int i = 0; i < 8; i++) {
                int f4 = tid + i * 256;
                int row = f4 >> 4, c8 = (f4 & 15) * 8;
                float4 v = *reinterpret_cast<float4*>(pst + row * PSTR + c8);
                *reinterpret_cast<float4*>(
                    g_attb + ((size_t)b * Nn + m0 + row) * Nn + n0 + c8) = v;
            }
            // reset acc for next chunk
            #pragma unroll
            for (int mf = 0; mf < 4; mf++)
                #pragma unroll
                for (int nf = 0; nf < 4; nf++)
                    #pragma unroll
                    for (int k = 0; k < 4; k++) acc[mf][nf][k] = 0.0f;
        }
    }
}

// ---------------------------------------------------------------------------
// Kernel 4: AV, 512 threads, 128(m) x 256(c) tile — attb read ONCE per m-tile.
// 16 warps (wy 0..1, wx 0..7), 3-stage ring: A 128 rows + B(v) 256 rows.
// grid (32 mtile, 1, B), dynamic smem 92160.
// ---------------------------------------------------------------------------
__global__ __launch_bounds__(512, 1) void av_kernel(
    const float* __restrict__ x, const float* __restrict__ mask,
    const float* __restrict__ skin, const float* __restrict__ gamma,
    float* __restrict__ out)
{
    extern __shared__ __align__(128) char dynsm[];
    __shared__ float fmv[128];
    __shared__ float szv[128];
    const int b = blockIdx.z, m0 = blockIdx.x * 128;
    const int tid = threadIdx.x, wid = tid >> 5, lane = tid & 31;
    const int wy = wid >> 3, wx = wid & 7;
    const uint32_t sb = smem_u32(dynsm);

    if (tid < 128) {
        fmv[tid] = mask[(size_t)b * Nn + m0 + tid] * skin[(size_t)b * Nn + m0 + tid];
        const float4* sp = reinterpret_cast<const float4*>(
            g_sumexp + ((size_t)b * Nn + m0 + tid) * 32);
        float s = 0.0f;
        #pragma unroll
        for (int i = 0; i < 8; i++) {
            float4 v = sp[i];
            s += (v.x + v.y) + (v.z + v.w);
        }
        szv[tid] = 1.0f / s;
    }

    const __half* Asrc = reinterpret_cast<const __half*>(g_attb + ((size_t)b * Nn + m0) * Nn);
    const __half* Bsrc = reinterpret_cast<const __half*>(g_vb + (size_t)b * Cc * Nn);

    const int NK = Nn / 32;   // 128
    #pragma unroll
    for (int s = 0; s < 2; s++) {
        uint32_t st = sb + s * AV_STAGE;
        load_a512(st, Asrc + s * 32, Nn, tid);
        load_b512(st + AV_ATILE, Bsrc + s * 32, Nn, tid);
        CP_COMMIT();
    }

    float acc[4][4][4] = {};
    #pragma unroll 1
    for (int s = 0; s < NK; s++) {
        if (s < NK - 1) cp_wait<1>(); else cp_wait<0>();
        __syncthreads();
        if (s + 2 < NK) {
            uint32_t ld = sb + (uint32_t)((s + 2) % NSTAGE) * AV_STAGE;
            load_a512(ld, Asrc + (s + 2) * 32, Nn, tid);
            load_b512(ld + AV_ATILE, Bsrc + (s + 2) * 32, Nn, tid);
            CP_COMMIT();
        }
        const uint32_t st = sb + (uint32_t)(s % NSTAGE) * AV_STAGE;
        warp_mma_step_bf(acc, st, st + AV_ATILE, wy, wx, lane);
    }

    // Fused epilogue: out[c][m] = gamma*fm[m]*zinv[m]*D[m][c] + x[c][m]
    const float gm = __ldg(gamma);
    #pragma unroll
    for (int mf = 0; mf < 4; mf++) {
        const int ml = wy * 64 + mf * 16 + (lane >> 2);    // local m (0..127)
        const float f0 = gm * fmv[ml] * szv[ml];
        const float f1 = gm * fmv[ml + 8] * szv[ml + 8];
        #pragma unroll
        for (int nf = 0; nf < 4; nf++) {
            const int c = wx * 32 + nf * 8 + (lane & 3) * 2;   // 0..255
            const size_t b0i = ((size_t)b * Cc + c) * Nn + m0 + ml;
            const size_t b1i = b0i + Nn;   // c+1
            out[b0i]     = fmaf(f0, acc[mf][nf][0], x[b0i]);
            out[b1i]     = fmaf(f0, acc[mf][nf][1], x[b1i]);
            out[b0i + 8] = fmaf(f1, acc[mf][nf][2], x[b0i + 8]);
            out[b1i + 8] = fmaf(f1, acc[mf][nf][3], x[b1i + 8]);
        }
    }
}

// ---------------------------------------------------------------------------
extern "C" void kernel_launch(void* const* d_in, const int* in_sizes, int n_in,
                              void* d_out, int out_size)
{
    (void)in_sizes; (void)n_in; (void)out_size;
    const float* x     = (const float*)d_in[0];
    const float* mask  = (const float*)d_in[1];
    const float* skin  = (const float*)d_in[2];
    const float* Wq    = (const float*)d_in[3];
    const float* bq    = (const float*)d_in[4];
    const float* Wk    = (const float*)d_in[5];
    const float* bk    = (const float*)d_in[6];
    const float* Wv    = (const float*)d_in[7];
    const float* bv    = (const float*)d_in[8];
    const float* gamma = (const float*)d_in[9];
    float* out = (float*)d_out;

    cudaFuncSetAttribute(projmma_kernel, cudaFuncAttributeMaxDynamicSharedMemorySize, DYN_SMEM);
    cudaFuncSetAttribute(qk_kernel, cudaFuncAttributeMaxDynamicSharedMemorySize, DYN_QK);
    cudaFuncSetAttribute(av_kernel, cudaFuncAttributeMaxDynamicSharedMemorySize, DYN_AV);

    dim3 gX(64, 4, Bb);
    xcvt_kernel<<<gX, 256>>>(x);

    wcvt_kernel<<<128, 256>>>(Wq, Wk, Wv);

    dim3 gP(4, 32, Bb);
    projmma_kernel<<<gP, 256, DYN_SMEM>>>(mask, skin, bq, bk, bv);

    dim3 gQK(8, 32, Bb);
    qk_kernel<<<gQK, 256, DYN_QK>>>();

    dim3 gAV(32, 1, Bb);
    av_kernel<<<gAV, 512, DYN_AV>>>(x, mask, skin, gamma, out);
}